// round 8
// baseline (speedup 1.0000x reference)
#include <cuda_runtime.h>

// Problem constants
#define IMG_H 512
#define IMG_W 512
#define NIMG  64
#define NPIX  (NIMG * IMG_H * IMG_W)   // 16,777,216

#define TILE_W   32
#define TILE_H   64
#define HALO     5
#define SW_H     74          // TILE_H + 2*HALO
#define PAD_L    8           // left pad (>= HALO, quad aligned)
#define XY_W     48          // padded strip width in packed elems (12 quads)
#define NTHREADS 512
#define GRID_X   (IMG_W / TILE_W)   // 16
#define GRID_Y   (IMG_H / TILE_H)   // 8
#define NBLOCKS  (GRID_X * GRID_Y * NIMG)   // 8192

// SMEM layout (bytes):
//  xy   : 74*48*8  = 28416   packed (x,y) inputs
//  pmu  : 74*32*8  = 18944   (mu1,mu2) plane (float2)
//  psg  : 74*32*8  = 18944   (sxx,syy) plane (float2)
//  pe   : 74*32*4  =  9472   sxy plane
#define XY_BYTES   (SW_H * XY_W * 8)
#define PMU_BYTES  (SW_H * TILE_W * 8)
#define PSG_BYTES  (SW_H * TILE_W * 8)
#define SMEM_BYTES (XY_BYTES + PMU_BYTES + PSG_BYTES + SW_H * TILE_W * 4) // 75,776 -> 3 CTAs/SM

// Separable Gaussian (sigma=1.5, 11 taps), normalized.
#define W0 0.00102838f
#define W1 0.00759876f
#define W2 0.03600077f
#define W3 0.10936060f
#define W4 0.21300553f
#define W5 0.26601172f
__device__ constexpr float GW[11] = {W0, W1, W2, W3, W4, W5, W4, W3, W2, W1, W0};
#define GPI(t) ((t) < 6 ? (t) : 10 - (t))

typedef unsigned long long ull;

__device__ __forceinline__ ull pack2(float lo, float hi) {
    ull d;
    asm("mov.b64 %0, {%1, %2};" : "=l"(d) : "r"(__float_as_uint(lo)), "r"(__float_as_uint(hi)));
    return d;
}
__device__ __forceinline__ void unpack2(ull v, float& lo, float& hi) {
    unsigned r0, r1;
    asm("mov.b64 {%0, %1}, %2;" : "=r"(r0), "=r"(r1) : "l"(v));
    lo = __uint_as_float(r0); hi = __uint_as_float(r1);
}
__device__ __forceinline__ ull fma2(ull a, ull b, ull c) {
    ull d;
    asm("fma.rn.f32x2 %0, %1, %2, %3;" : "=l"(d) : "l"(a), "l"(b), "l"(c));
    return d;
}
__device__ __forceinline__ ull mul2(ull a, ull b) {
    ull d;
    asm("mul.rn.f32x2 %0, %1, %2;" : "=l"(d) : "l"(a), "l"(b));
    return d;
}

__device__ float g_partials[NBLOCKS];
__device__ int   g_count = 0;

extern __shared__ char smem_raw[];

__global__ __launch_bounds__(NTHREADS, 3)
void ssim_fused_kernel(const float* __restrict__ img1, const float* __restrict__ img2,
                       float* __restrict__ out) {
    ull*    xy  = (ull*)smem_raw;                                        // 74x48 packed (x,y)
    ull*    pmu = (ull*)(smem_raw + XY_BYTES);                           // (mu1,mu2) plane
    ull*    psg = (ull*)(smem_raw + XY_BYTES + PMU_BYTES);               // (sxx,syy) plane
    float*  pe  = (float*)(smem_raw + XY_BYTES + PMU_BYTES + PSG_BYTES); // sxy plane

    const int tid = threadIdx.x;
    const int img = blockIdx.z;
    const int r0  = blockIdx.y * TILE_H;
    const int c0  = blockIdx.x * TILE_W;
    const float* p1 = img1 + (size_t)img * (IMG_H * IMG_W);
    const float* p2 = img2 + (size_t)img * (IMG_H * IMG_W);

    // Packed Gaussian weight pairs (horizontal pass only; vertical uses FFMA-imm)
    ull gp[6];
    gp[0] = pack2(W0, W0); gp[1] = pack2(W1, W1); gp[2] = pack2(W2, W2);
    gp[3] = pack2(W3, W3); gp[4] = pack2(W4, W4); gp[5] = pack2(W5, W5);

    // ---- Load halo strip: unit = (row, quad of 4 cols) ----
    for (int u = tid; u < SW_H * (XY_W / 4); u += NTHREADS) {
        int r = u / (XY_W / 4);
        int q = u - r * (XY_W / 4);
        int gr = r0 + r - HALO;
        int gc = c0 - PAD_L + q * 4;
        float4 vx = make_float4(0.f, 0.f, 0.f, 0.f);
        float4 vy = vx;
        if (gr >= 0 && gr < IMG_H && gc >= 0 && gc + 3 < IMG_W) {
            vx = *(const float4*)(p1 + (size_t)gr * IMG_W + gc);
            vy = *(const float4*)(p2 + (size_t)gr * IMG_W + gc);
        }
        ulonglong2* dst = (ulonglong2*)(xy + r * XY_W + q * 4);
        dst[0] = make_ulonglong2(pack2(vx.x, vy.x), pack2(vx.y, vy.y));
        dst[1] = make_ulonglong2(pack2(vx.z, vy.z), pack2(vx.w, vy.w));
    }
    __syncthreads();

    // ---- Horizontal pass: unit = (row, 4 output cols); 74*8 = 592 units ----
    for (int unit = tid; unit < SW_H * (TILE_W / 4); unit += NTHREADS) {
        int row = unit >> 3;
        int cb  = (unit & 7) * 4;

        ull v[16];
        const ulonglong2* vr = (const ulonglong2*)(xy + row * XY_W + cb + 2);
        #pragma unroll
        for (int i = 0; i < 8; i++) {
            ulonglong2 t = vr[i];
            v[2 * i]     = t.x;
            v[2 * i + 1] = t.y;
        }

        const int o = row * TILE_W + cb;

        // Sweep A: packed (mu1,mu2) conv + scalar sxy conv
        ull   mu[4]  = {0, 0, 0, 0};
        float sxy[4] = {0, 0, 0, 0};
        #pragma unroll
        for (int k = 1; k < 15; k++) {
            float x, y;
            unpack2(v[k], x, y);
            float e = x * y;
            #pragma unroll
            for (int j = 0; j < 4; j++) {
                const int t = k - 1 - j;
                if (t >= 0 && t < 11) {
                    mu[j]  = fma2(gp[GPI(t)], v[k], mu[j]);
                    sxy[j] = fmaf(GW[t], e, sxy[j]);
                }
            }
        }
        // Sweep B: packed (sxx,syy) conv
        ull sg[4] = {0, 0, 0, 0};
        #pragma unroll
        for (int k = 1; k < 15; k++) {
            ull p = mul2(v[k], v[k]);
            #pragma unroll
            for (int j = 0; j < 4; j++) {
                const int t = k - 1 - j;
                if (t >= 0 && t < 11)
                    sg[j] = fma2(gp[GPI(t)], p, sg[j]);
            }
        }
        // SoA plane stores (o multiple of 4 -> 16B aligned vector stores)
        ulonglong2* pm2 = (ulonglong2*)(pmu + o);
        pm2[0] = make_ulonglong2(mu[0], mu[1]);
        pm2[1] = make_ulonglong2(mu[2], mu[3]);
        ulonglong2* ps2 = (ulonglong2*)(psg + o);
        ps2[0] = make_ulonglong2(sg[0], sg[1]);
        ps2[1] = make_ulonglong2(sg[2], sg[3]);
        *(float4*)(pe + o) = make_float4(sxy[0], sxy[1], sxy[2], sxy[3]);
    }
    __syncthreads();

    // ---- Vertical pass + SSIM: 8 groups x 32 cols, 8 rows/thread (256 active) ----
    float local = 0.f;
    const float C1 = 0.0001f;
    const float C2 = 0.0009f;

    if (tid < 256) {
        const int col = tid & (TILE_W - 1);
        const int rb  = (tid >> 5) * 8;     // output rows rb..rb+7; taps rb..rb+17

        // Sweep 1: mu plane -> P = mu1*mu2, S = mu1^2 + mu2^2
        float P[8], S[8];
        {
            float m1[8] = {0,0,0,0,0,0,0,0};
            float m2[8] = {0,0,0,0,0,0,0,0};
            #pragma unroll
            for (int k = 0; k < 18; k++) {
                const float2 mv = *(const float2*)(pmu + (rb + k) * TILE_W + col);
                #pragma unroll
                for (int j = 0; j < 8; j++) {
                    const int t = k - j;
                    if (t >= 0 && t < 11) {
                        m1[j] = fmaf(GW[t], mv.x, m1[j]);
                        m2[j] = fmaf(GW[t], mv.y, m2[j]);
                    }
                }
            }
            #pragma unroll
            for (int j = 0; j < 8; j++) {
                P[j] = m1[j] * m2[j];
                S[j] = fmaf(m1[j], m1[j], m2[j] * m2[j]);
            }
        }

        // Sweep 2: sig plane -> den = (S+C1) * (sxx+syy-S+C2)
        float den[8];
        {
            float sxx[8] = {0,0,0,0,0,0,0,0};
            float syy[8] = {0,0,0,0,0,0,0,0};
            #pragma unroll
            for (int k = 0; k < 18; k++) {
                const float2 sv = *(const float2*)(psg + (rb + k) * TILE_W + col);
                #pragma unroll
                for (int j = 0; j < 8; j++) {
                    const int t = k - j;
                    if (t >= 0 && t < 11) {
                        sxx[j] = fmaf(GW[t], sv.x, sxx[j]);
                        syy[j] = fmaf(GW[t], sv.y, syy[j]);
                    }
                }
            }
            #pragma unroll
            for (int j = 0; j < 8; j++)
                den[j] = (S[j] + C1) * (sxx[j] + syy[j] - S[j] + C2);
        }

        // Sweep 3: sxy plane -> num, accumulate ssim
        {
            float axy[8] = {0,0,0,0,0,0,0,0};
            #pragma unroll
            for (int k = 0; k < 18; k++) {
                const float e = pe[(rb + k) * TILE_W + col];
                #pragma unroll
                for (int j = 0; j < 8; j++) {
                    const int t = k - j;
                    if (t >= 0 && t < 11)
                        axy[j] = fmaf(GW[t], e, axy[j]);
                }
            }
            #pragma unroll
            for (int j = 0; j < 8; j++) {
                float num = (2.f * P[j] + C1) * (2.f * (axy[j] - P[j]) + C2);
                local += __fdividef(num, den[j]);
            }
        }
    }

    // ---- Block reduction (fixed order -> deterministic) ----
    #pragma unroll
    for (int off = 16; off > 0; off >>= 1)
        local += __shfl_xor_sync(0xffffffffu, local, off);

    __shared__ float wsum[NTHREADS / 32];
    __shared__ int   s_last;
    if ((tid & 31) == 0) wsum[tid >> 5] = local;
    __syncthreads();
    if (tid == 0) {
        float s = 0.f;
        #pragma unroll
        for (int w = 0; w < NTHREADS / 32; w++) s += wsum[w];
        int bid = (blockIdx.z * gridDim.y + blockIdx.y) * gridDim.x + blockIdx.x;
        g_partials[bid] = s;
        __threadfence();
        int old = atomicAdd(&g_count, 1);
        s_last = (old == NBLOCKS - 1);
    }
    __syncthreads();

    // ---- Last block: deterministic final reduction in fp64, reset counter ----
    if (s_last) {
        __threadfence();
        __shared__ double dsh[NTHREADS / 32];
        double acc = 0.0;
        const int per = NBLOCKS / NTHREADS;   // 16
        for (int i = 0; i < per; i++)
            acc += (double)g_partials[tid * per + i];
        #pragma unroll
        for (int off = 16; off > 0; off >>= 1)
            acc += __shfl_xor_sync(0xffffffffu, acc, off);
        if ((tid & 31) == 0) dsh[tid >> 5] = acc;
        __syncthreads();
        if (tid == 0) {
            double s = 0.0;
            #pragma unroll
            for (int w = 0; w < NTHREADS / 32; w++) s += dsh[w];
            out[0] = (float)(1.0 - s * (1.0 / (double)NPIX));
            g_count = 0;   // reset for next graph replay
        }
    }
}

extern "C" void kernel_launch(void* const* d_in, const int* in_sizes, int n_in,
                              void* d_out, int out_size) {
    const float* pred   = (const float*)d_in[0];
    const float* target = (const float*)d_in[1];
    float* out = (float*)d_out;

    cudaFuncSetAttribute(ssim_fused_kernel,
                         cudaFuncAttributeMaxDynamicSharedMemorySize, SMEM_BYTES);

    dim3 grid(GRID_X, GRID_Y, NIMG);   // (16, 8, 64)
    ssim_fused_kernel<<<grid, NTHREADS, SMEM_BYTES>>>(pred, target, out);
}

// round 9
// speedup vs baseline: 1.3684x; 1.3684x over previous
#include <cuda_runtime.h>

// Problem constants
#define IMG_H 512
#define IMG_W 512
#define NIMG  64
#define NPIX  (NIMG * IMG_H * IMG_W)   // 16,777,216

#define TILE_W   32
#define TILE_H   64
#define HALO     5
#define SW_H     74          // TILE_H + 2*HALO
#define PAD_L    8           // left pad (>= HALO, quad aligned)
#define XY_W     48          // padded strip width in packed elems (12 quads)
#define NTHREADS 512
#define GRID_X   (IMG_W / TILE_W)   // 16
#define GRID_Y   (IMG_H / TILE_H)   // 8
#define NBLOCKS  (GRID_X * GRID_Y * NIMG)   // 8192

// SMEM layout (bytes):
//  xy  : 74*48*8  = 28416   packed (x,y) inputs
//  mid : 74*32*16 = 37888   {(mu1,mu2), (x2+y2, xy)} per elem (ulonglong2)
#define XY_BYTES   (SW_H * XY_W * 8)
#define SMEM_BYTES (XY_BYTES + SW_H * TILE_W * 16)   // 66,304 -> 3 CTAs/SM

// Separable Gaussian (sigma=1.5, 11 taps), normalized.
#define W0 0.00102838f
#define W1 0.00759876f
#define W2 0.03600077f
#define W3 0.10936060f
#define W4 0.21300553f
#define W5 0.26601172f
__device__ constexpr float GW[11] = {W0, W1, W2, W3, W4, W5, W4, W3, W2, W1, W0};
#define GPI(t) ((t) < 6 ? (t) : 10 - (t))

typedef unsigned long long ull;

__device__ __forceinline__ ull pack2(float lo, float hi) {
    ull d;
    asm("mov.b64 %0, {%1, %2};" : "=l"(d) : "r"(__float_as_uint(lo)), "r"(__float_as_uint(hi)));
    return d;
}
__device__ __forceinline__ void unpack2(ull v, float& lo, float& hi) {
    unsigned r0, r1;
    asm("mov.b64 {%0, %1}, %2;" : "=r"(r0), "=r"(r1) : "l"(v));
    lo = __uint_as_float(r0); hi = __uint_as_float(r1);
}
__device__ __forceinline__ ull fma2(ull a, ull b, ull c) {
    ull d;
    asm("fma.rn.f32x2 %0, %1, %2, %3;" : "=l"(d) : "l"(a), "l"(b), "l"(c));
    return d;
}

__device__ float g_partials[NBLOCKS];
__device__ int   g_count = 0;

extern __shared__ char smem_raw[];

__global__ __launch_bounds__(NTHREADS, 3)
void ssim_fused_kernel(const float* __restrict__ img1, const float* __restrict__ img2,
                       float* __restrict__ out) {
    ull*        xy   = (ull*)smem_raw;                      // 74x48 packed (x,y)
    ulonglong2* midm = (ulonglong2*)(smem_raw + XY_BYTES);  // {(mu1,mu2),(z,xy)}

    const int tid = threadIdx.x;
    const int img = blockIdx.z;
    const int r0  = blockIdx.y * TILE_H;
    const int c0  = blockIdx.x * TILE_W;
    const float* p1 = img1 + (size_t)img * (IMG_H * IMG_W);
    const float* p2 = img2 + (size_t)img * (IMG_H * IMG_W);

    // Packed Gaussian weight pairs (6 distinct by symmetry)
    ull gp[6];
    gp[0] = pack2(W0, W0); gp[1] = pack2(W1, W1); gp[2] = pack2(W2, W2);
    gp[3] = pack2(W3, W3); gp[4] = pack2(W4, W4); gp[5] = pack2(W5, W5);

    // ---- Load halo strip: unit = (row, quad of 4 cols) ----
    // Strip covers global cols [c0-8, c0+40); every quad uniformly valid or OOB.
    for (int u = tid; u < SW_H * (XY_W / 4); u += NTHREADS) {
        int r = u / (XY_W / 4);
        int q = u - r * (XY_W / 4);
        int gr = r0 + r - HALO;
        int gc = c0 - PAD_L + q * 4;
        float4 vx = make_float4(0.f, 0.f, 0.f, 0.f);
        float4 vy = vx;
        if (gr >= 0 && gr < IMG_H && gc >= 0 && gc + 3 < IMG_W) {
            vx = *(const float4*)(p1 + (size_t)gr * IMG_W + gc);
            vy = *(const float4*)(p2 + (size_t)gr * IMG_W + gc);
        }
        ulonglong2* dst = (ulonglong2*)(xy + r * XY_W + q * 4);
        dst[0] = make_ulonglong2(pack2(vx.x, vy.x), pack2(vx.y, vy.y));
        dst[1] = make_ulonglong2(pack2(vx.z, vy.z), pack2(vx.w, vy.w));
    }
    __syncthreads();

    // ---- Horizontal pass: unit = (row, 4 output cols); 74*8 = 592 units ----
    for (int unit = tid; unit < SW_H * (TILE_W / 4); unit += NTHREADS) {
        int row = unit >> 3;
        int cb  = (unit & 7) * 4;

        // Needed input col n lives at smem col n + (PAD_L - HALO) = n + 3.
        // Load 16 packed starting at smem col cb+2 (16B aligned); use v[1..14].
        ull v[16];
        const ulonglong2* vr = (const ulonglong2*)(xy + row * XY_W + cb + 2);
        #pragma unroll
        for (int i = 0; i < 8; i++) {
            ulonglong2 t = vr[i];
            v[2 * i]     = t.x;
            v[2 * i + 1] = t.y;
        }

        const int o = row * TILE_W + cb;

        // Sweep A: packed (mu1,mu2) conv
        ull mu[4] = {0, 0, 0, 0};
        #pragma unroll
        for (int k = 1; k < 15; k++) {
            #pragma unroll
            for (int j = 0; j < 4; j++) {
                const int t = k - 1 - j;
                if (t >= 0 && t < 11)
                    mu[j] = fma2(gp[GPI(t)], v[k], mu[j]);
            }
        }
        // Sweep B: packed (z, xy) conv where z = x^2 + y^2
        ull sz[4] = {0, 0, 0, 0};
        #pragma unroll
        for (int k = 1; k < 15; k++) {
            float x, y;
            unpack2(v[k], x, y);
            const float e = x * y;
            const float z = fmaf(x, x, y * y);
            const ull   w = pack2(z, e);
            #pragma unroll
            for (int j = 0; j < 4; j++) {
                const int t = k - 1 - j;
                if (t >= 0 && t < 11)
                    sz[j] = fma2(gp[GPI(t)], w, sz[j]);
            }
        }
        #pragma unroll
        for (int j = 0; j < 4; j++)
            midm[o + j] = make_ulonglong2(mu[j], sz[j]);
    }
    __syncthreads();

    // ---- Vertical pass + SSIM: 16 groups x 32 cols, 4 rows/thread ----
    float local = 0.f;
    const int col = tid & (TILE_W - 1);
    const int rb  = (tid >> 5) * 4;

    const float C1 = 0.0001f;
    const float C2 = 0.0009f;

    {
        ull amu[4] = {0, 0, 0, 0};
        ull asz[4] = {0, 0, 0, 0};

        #pragma unroll
        for (int k = 0; k < 14; k++) {
            const ulonglong2 m = midm[(rb + k) * TILE_W + col];
            #pragma unroll
            for (int j = 0; j < 4; j++) {
                const int t = k - j;
                if (t >= 0 && t < 11) {
                    const ull gpt = gp[GPI(t)];
                    amu[j] = fma2(gpt, m.x, amu[j]);
                    asz[j] = fma2(gpt, m.y, asz[j]);
                }
            }
        }

        #pragma unroll
        for (int j = 0; j < 4; j++) {
            float mu1, mu2, z, exy;
            unpack2(amu[j], mu1, mu2);
            unpack2(asz[j], z, exy);
            const float S   = fmaf(mu1, mu1, mu2 * mu2);   // mu1^2 + mu2^2
            const float P   = mu1 * mu2;
            const float s12 = exy - P;                     // sigma12
            const float sig = z - S;                       // sigma1^2 + sigma2^2
            const float num = (2.f * P + C1) * (2.f * s12 + C2);
            const float den = (S + C1) * (sig + C2);
            local += __fdividef(num, den);
        }
    }

    // ---- Block reduction (fixed order -> deterministic) ----
    #pragma unroll
    for (int off = 16; off > 0; off >>= 1)
        local += __shfl_xor_sync(0xffffffffu, local, off);

    __shared__ float wsum[NTHREADS / 32];
    __shared__ int   s_last;
    if ((tid & 31) == 0) wsum[tid >> 5] = local;
    __syncthreads();
    if (tid == 0) {
        float s = 0.f;
        #pragma unroll
        for (int w = 0; w < NTHREADS / 32; w++) s += wsum[w];
        int bid = (blockIdx.z * gridDim.y + blockIdx.y) * gridDim.x + blockIdx.x;
        g_partials[bid] = s;
        __threadfence();
        int old = atomicAdd(&g_count, 1);
        s_last = (old == NBLOCKS - 1);
    }
    __syncthreads();

    // ---- Last block: deterministic final reduction in fp64, reset counter ----
    if (s_last) {
        __threadfence();
        __shared__ double dsh[NTHREADS / 32];
        double acc = 0.0;
        const int per = NBLOCKS / NTHREADS;   // 16
        for (int i = 0; i < per; i++)
            acc += (double)g_partials[tid * per + i];
        #pragma unroll
        for (int off = 16; off > 0; off >>= 1)
            acc += __shfl_xor_sync(0xffffffffu, acc, off);
        if ((tid & 31) == 0) dsh[tid >> 5] = acc;
        __syncthreads();
        if (tid == 0) {
            double s = 0.0;
            #pragma unroll
            for (int w = 0; w < NTHREADS / 32; w++) s += dsh[w];
            out[0] = (float)(1.0 - s * (1.0 / (double)NPIX));
            g_count = 0;   // reset for next graph replay
        }
    }
}

extern "C" void kernel_launch(void* const* d_in, const int* in_sizes, int n_in,
                              void* d_out, int out_size) {
    const float* pred   = (const float*)d_in[0];
    const float* target = (const float*)d_in[1];
    float* out = (float*)d_out;

    cudaFuncSetAttribute(ssim_fused_kernel,
                         cudaFuncAttributeMaxDynamicSharedMemorySize, SMEM_BYTES);

    dim3 grid(GRID_X, GRID_Y, NIMG);   // (16, 8, 64)
    ssim_fused_kernel<<<grid, NTHREADS, SMEM_BYTES>>>(pred, target, out);
}